// round 13
// baseline (speedup 1.0000x reference)
#include <cuda_runtime.h>
#include <cuda_fp16.h>
#include <cuda_bf16.h>
#include <cstdint>
#include <math.h>

// Problem constants (fixed dataset)
#define Nn 50000
#define Ee 600000
#define Hh 128
#define Gg 512
#define HPd 25
#define Cc 1000
#define SCAN_BLK 1024
#define NBLK ((Nn + SCAN_BLK - 1) / SCAN_BLK)   // 49

// ---------------- device scratch ----------------
// INVARIANT: g_cnt and g_cur are all-zero on entry to kernel_launch.
// (BSS starts zeroed; k_scan_blocks re-zeros g_cnt, agg layer-1 re-zeros g_cur.)
__device__ __half g_h[Nn * Hh];     // h = x @ W (fp16, current layer)
__device__ float g_x[Nn * Hh];
__device__ float g_as[Nn];
__device__ float g_ad[Nn];
__device__ float g_energy[Nn];
__device__ int   g_cnt[Nn];
__device__ int   g_cur[Nn];
__device__ int   g_off[Nn + 1];
__device__ int   g_csr[Ee];
__device__ int   g_bsum[NBLK];
__device__ float g_pooled[Gg * Hh];

// ---------------- helpers ----------------
__device__ __forceinline__ float leaky(float v) { return v > 0.f ? v : 0.2f * v; }
__device__ __forceinline__ float wred_max(float v) {
    #pragma unroll
    for (int o = 16; o; o >>= 1) v = fmaxf(v, __shfl_xor_sync(0xffffffffu, v, o));
    return v;
}
__device__ __forceinline__ float wred_sum(float v) {
    #pragma unroll
    for (int o = 16; o; o >>= 1) v += __shfl_xor_sync(0xffffffffu, v, o);
    return v;
}
__device__ __forceinline__ float to_tf32(float v) {
    uint32_t u;
    asm("cvt.rna.tf32.f32 %0, %1;" : "=r"(u) : "f"(v));
    return __uint_as_float(u);
}
__device__ __forceinline__ void mma_tf32(float c[4], const uint32_t a[4], const uint32_t b[2]) {
    asm volatile(
        "mma.sync.aligned.m16n8k8.row.col.f32.tf32.tf32.f32 "
        "{%0,%1,%2,%3}, {%4,%5,%6,%7}, {%8,%9}, {%0,%1,%2,%3};"
        : "+f"(c[0]), "+f"(c[1]), "+f"(c[2]), "+f"(c[3])
        : "r"(a[0]), "r"(a[1]), "r"(a[2]), "r"(a[3]), "r"(b[0]), "r"(b[1]));
}

// ---------------- CSR build ----------------
__global__ void k_hist(const int* __restrict__ dst) {
    int i = blockIdx.x * blockDim.x + threadIdx.x;
    if (i < Ee) atomicAdd(&g_cnt[dst[i]], 1);
}

// parallel per-block scan (coalesced); re-zeros g_cnt after reading
__global__ void k_scan_blocks() {
    __shared__ int s[SCAN_BLK];
    int t = threadIdx.x;
    int i = blockIdx.x * SCAN_BLK + t;
    int v = (i < Nn) ? g_cnt[i] : 0;
    if (i < Nn) g_cnt[i] = 0;
    s[t] = v;
    __syncthreads();
    #pragma unroll
    for (int off = 1; off < SCAN_BLK; off <<= 1) {
        int x = 0;
        if (t >= off) x = s[t - off];
        __syncthreads();
        s[t] += x;
        __syncthreads();
    }
    if (i < Nn) g_off[i] = s[t] - v;          // exclusive within block
    if (t == SCAN_BLK - 1) g_bsum[blockIdx.x] = s[t];
}

// add cross-block prefix; each block computes the <=49-element bsum scan itself
__global__ void k_add_prefix() {
    __shared__ int pre[NBLK];
    int t = threadIdx.x;
    if (t < 32) {
        int l = t;
        int a = (l < NBLK) ? g_bsum[l] : 0;
        int b = (l + 32 < NBLK) ? g_bsum[l + 32] : 0;
        int A = a, B = b;
        #pragma unroll
        for (int o = 1; o < 32; o <<= 1) {
            int t1 = __shfl_up_sync(0xffffffffu, A, o);
            int t2 = __shfl_up_sync(0xffffffffu, B, o);
            if (l >= o) { A += t1; B += t2; }
        }
        int totA = __shfl_sync(0xffffffffu, A, 31);
        if (l < NBLK) pre[l] = A - a;
        if (l + 32 < NBLK) pre[l + 32] = totA + B - b;
    }
    __syncthreads();
    int i = blockIdx.x * blockDim.x + t;
    if (i < Nn) g_off[i] += pre[i >> 10];
    else if (i == Nn) g_off[Nn] = Ee;
}

__global__ void k_scatter(const int* __restrict__ src, const int* __restrict__ dst) {
    int i = blockIdx.x * blockDim.x + threadIdx.x;
    if (i < Ee) {
        int d = dst[i];
        int pos = g_off[d] + atomicAdd(&g_cur[d], 1);
        g_csr[pos] = src[i];
    }
}

// ---------------- TF32 tensor-core GEMM + fused attention dots ----------------
// g_h[M,128] (fp16) = X[M,128] @ W[128,128];  g_as = h.a_src, g_ad = h.a_dst
__global__ void __launch_bounds__(256) k_gemm128(
        const float* __restrict__ Xext, int src_sel,
        const float* __restrict__ W,
        const float* __restrict__ a_src, const float* __restrict__ a_dst, int M) {
    const float* __restrict__ X = src_sel ? (const float*)g_x : Xext;
    __shared__ float Xs[128][36];
    __shared__ float Ws[32][136];
    __shared__ float sd_as[2][128];
    __shared__ float sd_ad[2][128];

    int tid = threadIdx.x;
    int lane = tid & 31, wid = tid >> 5;
    int wm = wid >> 1, wn = wid & 1;
    int gid = lane >> 2, tig = lane & 3;
    int row0 = blockIdx.x * 128;

    float acc[2][8][4];
    #pragma unroll
    for (int mt = 0; mt < 2; mt++)
        #pragma unroll
        for (int nt = 0; nt < 8; nt++)
            #pragma unroll
            for (int q = 0; q < 4; q++) acc[mt][nt][q] = 0.f;

    #pragma unroll 1
    for (int kc = 0; kc < 4; kc++) {
        #pragma unroll
        for (int l = 0; l < 4; l++) {
            int f = tid + l * 256;
            int r = f >> 3, c4 = f & 7;
            int gr = row0 + r;
            float4 v = make_float4(0.f, 0.f, 0.f, 0.f);
            if (gr < M) v = reinterpret_cast<const float4*>(&X[gr * 128 + kc * 32])[c4];
            Xs[r][c4 * 4 + 0] = to_tf32(v.x);
            Xs[r][c4 * 4 + 1] = to_tf32(v.y);
            Xs[r][c4 * 4 + 2] = to_tf32(v.z);
            Xs[r][c4 * 4 + 3] = to_tf32(v.w);
        }
        #pragma unroll
        for (int l = 0; l < 4; l++) {
            int f = tid + l * 256;
            int k = f >> 5, c4 = f & 31;
            float4 v = reinterpret_cast<const float4*>(&W[(kc * 32 + k) * 128])[c4];
            Ws[k][c4 * 4 + 0] = to_tf32(v.x);
            Ws[k][c4 * 4 + 1] = to_tf32(v.y);
            Ws[k][c4 * 4 + 2] = to_tf32(v.z);
            Ws[k][c4 * 4 + 3] = to_tf32(v.w);
        }
        __syncthreads();
        #pragma unroll
        for (int ks = 0; ks < 4; ks++) {
            int k0 = ks * 8;
            uint32_t a[2][4];
            #pragma unroll
            for (int mt = 0; mt < 2; mt++) {
                int rb = wm * 32 + mt * 16;
                a[mt][0] = __float_as_uint(Xs[rb + gid][k0 + tig]);
                a[mt][1] = __float_as_uint(Xs[rb + gid + 8][k0 + tig]);
                a[mt][2] = __float_as_uint(Xs[rb + gid][k0 + tig + 4]);
                a[mt][3] = __float_as_uint(Xs[rb + gid + 8][k0 + tig + 4]);
            }
            uint32_t b[8][2];
            #pragma unroll
            for (int nt = 0; nt < 8; nt++) {
                int cb = wn * 64 + nt * 8 + gid;
                b[nt][0] = __float_as_uint(Ws[k0 + tig][cb]);
                b[nt][1] = __float_as_uint(Ws[k0 + tig + 4][cb]);
            }
            #pragma unroll
            for (int mt = 0; mt < 2; mt++)
                #pragma unroll
                for (int nt = 0; nt < 8; nt++)
                    mma_tf32(acc[mt][nt], a[mt], b[nt]);
        }
        __syncthreads();
    }

    // store h as fp16 (half2 per (mt,nt,half))
    #pragma unroll
    for (int mt = 0; mt < 2; mt++) {
        int r0 = row0 + wm * 32 + mt * 16 + gid;
        #pragma unroll
        for (int half = 0; half < 2; half++) {
            int gr = r0 + half * 8;
            if (gr < M) {
                #pragma unroll
                for (int nt = 0; nt < 8; nt++) {
                    int col = wn * 64 + nt * 8 + 2 * tig;
                    __half2 v = __floats2half2_rn(acc[mt][nt][2 * half + 0], acc[mt][nt][2 * half + 1]);
                    *reinterpret_cast<__half2*>(&g_h[gr * 128 + col]) = v;
                }
            }
        }
    }

    // fused attention dots
    float sa[8][2], sd[8][2];
    #pragma unroll
    for (int nt = 0; nt < 8; nt++) {
        int col = wn * 64 + nt * 8 + 2 * tig;
        sa[nt][0] = a_src[col]; sa[nt][1] = a_src[col + 1];
        sd[nt][0] = a_dst[col]; sd[nt][1] = a_dst[col + 1];
    }
    #pragma unroll
    for (int mt = 0; mt < 2; mt++) {
        #pragma unroll
        for (int half = 0; half < 2; half++) {
            float ps = 0.f, pd = 0.f;
            #pragma unroll
            for (int nt = 0; nt < 8; nt++) {
                ps += acc[mt][nt][2 * half + 0] * sa[nt][0] + acc[mt][nt][2 * half + 1] * sa[nt][1];
                pd += acc[mt][nt][2 * half + 0] * sd[nt][0] + acc[mt][nt][2 * half + 1] * sd[nt][1];
            }
            ps += __shfl_xor_sync(0xffffffffu, ps, 1);
            ps += __shfl_xor_sync(0xffffffffu, ps, 2);
            pd += __shfl_xor_sync(0xffffffffu, pd, 1);
            pd += __shfl_xor_sync(0xffffffffu, pd, 2);
            if (tig == 0) {
                int r = wm * 32 + mt * 16 + half * 8 + gid;
                sd_as[wn][r] = ps;
                sd_ad[wn][r] = pd;
            }
        }
    }
    __syncthreads();
    if (tid < 128) {
        int gr = row0 + tid;
        if (gr < M) {
            g_as[gr] = sd_as[0][tid] + sd_as[1][tid];
            g_ad[gr] = sd_ad[0][tid] + sd_ad[1][tid];
        }
    }
}

// ---------------- softmax aggregation (warp/node), online softmax, fp16 h ----------------
// ZEROCUR: also re-zero g_cur (consumed by k_scatter) to restore the entry invariant.
template <bool ELU, bool ENERGY, bool ZEROCUR>
__global__ void __launch_bounds__(256) k_aggregate(
        const float* __restrict__ bias,
        const float* __restrict__ Wp1, const float* __restrict__ bp1,
        const float* __restrict__ Wp2, const float* __restrict__ bp2) {
    __shared__ float WT[ENERGY ? HPd * 128 : 1];
    __shared__ float sb1[ENERGY ? HPd : 1];
    __shared__ float sw2[ENERGY ? HPd : 1];
    if (ZEROCUR) {
        int gi = blockIdx.x * blockDim.x + threadIdx.x;
        if (gi < Nn) g_cur[gi] = 0;
    }
    if (ENERGY) {
        for (int t = threadIdx.x; t < HPd * 128; t += blockDim.x) {
            int p = t >> 7, h = t & 127;
            WT[t] = Wp1[h * HPd + p];
        }
        if (threadIdx.x < HPd) { sb1[threadIdx.x] = bp1[threadIdx.x]; sw2[threadIdx.x] = Wp2[threadIdx.x]; }
        __syncthreads();
    }

    int w = (blockIdx.x * blockDim.x + threadIdx.x) >> 5;
    int lane = threadIdx.x & 31;
    if (w >= Nn) return;
    float adi = g_ad[w];
    float asi = g_as[w];
    int lo = g_off[w], hi = g_off[w + 1];

    float eself = leaky(asi + adi);
    // online pass: max + sum(exp), fast exp (MUFU)
    float m = (lane == 0) ? eself : -INFINITY;
    float ssum = (lane == 0) ? 1.f : 0.f;
    for (int j = lo + lane; j < hi; j += 32) {
        float e = leaky(g_as[g_csr[j]] + adi);
        if (e > m) { ssum *= __expf(m - e); m = e; }
        ssum += __expf(e - m);
    }
    float M = wred_max(m);
    ssum *= (m == -INFINITY) ? 0.f : __expf(m - M);
    ssum = wred_sum(ssum);
    float inv = 1.f / ssum;

    // weighted accumulate: lane owns 4 h-columns (one uint2 = 4 halves = 8B per row)
    // row stride in uint2 units: 128 halves * 2B / 8B = 32
    const uint2* hp = reinterpret_cast<const uint2*>(g_h);
    float wself = __expf(eself - M) * inv;
    uint2 rself = hp[w * 32 + lane];
    float2 f0 = __half22float2(*reinterpret_cast<__half2*>(&rself.x));
    float2 f1 = __half22float2(*reinterpret_cast<__half2*>(&rself.y));
    float4 acc = make_float4(wself * f0.x, wself * f0.y, wself * f1.x, wself * f1.y);
    for (int base = lo; base < hi; base += 32) {
        int j = base + lane;
        int sj = 0;
        float wj = 0.f;
        if (j < hi) {
            sj = g_csr[j];
            wj = __expf(leaky(g_as[sj] + adi) - M) * inv;
        }
        int cnt = min(32, hi - base);
        for (int q = 0; q < cnt; q++) {
            int   s  = __shfl_sync(0xffffffffu, sj, q);
            float ww = __shfl_sync(0xffffffffu, wj, q);
            uint2 r = hp[s * 32 + lane];
            float2 v0 = __half22float2(*reinterpret_cast<__half2*>(&r.x));
            float2 v1 = __half22float2(*reinterpret_cast<__half2*>(&r.y));
            acc.x += ww * v0.x; acc.y += ww * v0.y;
            acc.z += ww * v1.x; acc.w += ww * v1.y;
        }
    }
    // lane owns cols [4*lane, 4*lane+4): bias and output use the same mapping
    float4 b = reinterpret_cast<const float4*>(bias)[lane];
    acc.x += b.x; acc.y += b.y; acc.z += b.z; acc.w += b.w;
    if (ELU) {
        acc.x = acc.x > 0.f ? acc.x : expm1f(acc.x);
        acc.y = acc.y > 0.f ? acc.y : expm1f(acc.y);
        acc.z = acc.z > 0.f ? acc.z : expm1f(acc.z);
        acc.w = acc.w > 0.f ? acc.w : expm1f(acc.w);
    }
    reinterpret_cast<float4*>(g_x)[w * 32 + lane] = acc;

    if (ENERGY) {
        float e = bp2[0];
        #pragma unroll
        for (int p = 0; p < HPd; p++) {
            float4 wv = reinterpret_cast<const float4*>(&WT[p * 128])[lane];
            float part = acc.x * wv.x + acc.y * wv.y + acc.z * wv.z + acc.w * wv.w;
            float hid = wred_sum(part);
            e += fmaxf(hid + sb1[p], 0.f) * sw2[p];
        }
        if (lane == 0) g_energy[w] = e;
    }
}

// ---------------- segment-softmax pooling (block per segment g) ----------------
__global__ void __launch_bounds__(128) k_pool(const int* __restrict__ node_pos) {
    __shared__ float red[128];
    __shared__ float sw[128];
    int g = blockIdx.x;
    int t = threadIdx.x;
    int lo = node_pos[g], hi = node_pos[g + 1];
    if (lo >= hi) { g_pooled[g * 128 + t] = 0.f; return; }

    float local = -INFINITY;
    for (int n = lo + t; n < hi; n += 128) local = fmaxf(local, g_energy[n]);
    red[t] = local; __syncthreads();
    #pragma unroll
    for (int o = 64; o; o >>= 1) { if (t < o) red[t] = fmaxf(red[t], red[t + o]); __syncthreads(); }
    float m = red[0]; __syncthreads();

    local = 0.f;
    for (int n = lo + t; n < hi; n += 128) local += expf(g_energy[n] - m);
    red[t] = local; __syncthreads();
    #pragma unroll
    for (int o = 64; o; o >>= 1) { if (t < o) red[t] += red[t + o]; __syncthreads(); }
    float inv = 1.f / red[0];
    __syncthreads();

    float acc = 0.f;
    for (int chunk = lo; chunk < hi; chunk += 128) {
        int n = chunk + t;
        sw[t] = (n < hi) ? expf(g_energy[n] - m) * inv : 0.f;
        __syncthreads();
        int cnt = min(128, hi - chunk);
        #pragma unroll 4
        for (int q = 0; q < cnt; q++)
            acc += sw[q] * g_x[(chunk + q) * 128 + t];
        __syncthreads();
    }
    g_pooled[g * 128 + t] = acc;
}

// ---------------- classifier: out[G,C] = pooled @ Wl + bl ----------------
__global__ void __launch_bounds__(128) k_classify(
        const float* __restrict__ Wl, const float* __restrict__ bl,
        float* __restrict__ out) {
    __shared__ float sp[8][128];
    int g0 = blockIdx.y * 8;
    int c4 = blockIdx.x * 128 + threadIdx.x;
    for (int t = threadIdx.x; t < 8 * 128; t += 128) {
        int gi = t >> 7, k = t & 127;
        sp[gi][k] = g_pooled[(g0 + gi) * 128 + k];
    }
    __syncthreads();
    if (c4 >= Cc / 4) return;
    float4 acc[8];
    float4 blv = reinterpret_cast<const float4*>(bl)[c4];
    #pragma unroll
    for (int gi = 0; gi < 8; gi++) acc[gi] = blv;
    #pragma unroll 4
    for (int k = 0; k < 128; k++) {
        float4 wv = reinterpret_cast<const float4*>(&Wl[k * Cc])[c4];
        #pragma unroll
        for (int gi = 0; gi < 8; gi++) {
            float s = sp[gi][k];
            acc[gi].x += s * wv.x; acc[gi].y += s * wv.y;
            acc[gi].z += s * wv.z; acc[gi].w += s * wv.w;
        }
    }
    #pragma unroll
    for (int gi = 0; gi < 8; gi++)
        reinterpret_cast<float4*>(&out[(g0 + gi) * Cc])[c4] = acc[gi];
}

// ---------------- launch ----------------
extern "C" void kernel_launch(void* const* d_in, const int* in_sizes, int n_in,
                              void* d_out, int out_size) {
    const float* cfg_nodes = (const float*)d_in[0];
    const int*   rel       = (const int*)  d_in[1];
    const int*   node_pos  = (const int*)  d_in[2];
    const float* W_g1      = (const float*)d_in[3];
    const float* att_src1  = (const float*)d_in[4];
    const float* att_dst1  = (const float*)d_in[5];
    const float* b_g1      = (const float*)d_in[6];
    const float* W_g2      = (const float*)d_in[7];
    const float* att_src2  = (const float*)d_in[8];
    const float* att_dst2  = (const float*)d_in[9];
    const float* b_g2      = (const float*)d_in[10];
    const float* Wp1       = (const float*)d_in[11];
    const float* bp1       = (const float*)d_in[12];
    const float* Wp2       = (const float*)d_in[13];
    const float* bp2       = (const float*)d_in[14];
    const float* Wl        = (const float*)d_in[15];
    const float* bl        = (const float*)d_in[16];
    float* out = (float*)d_out;

    const int* e_src = rel;
    const int* e_dst = rel + Ee;

    int gemm_blocks = (Nn + 127) / 128;
    int warp_blocks = (Nn + 7) / 8;

    // gemm1 first (needs only inputs)
    k_gemm128<<<gemm_blocks, 256>>>(cfg_nodes, 0, W_g1, att_src1, att_dst1, Nn);

    // --- CSR build (parallel scan, coalesced; bsum scan folded into add_prefix) ---
    k_hist<<<(Ee + 255) / 256, 256>>>(e_dst);
    k_scan_blocks<<<NBLK, SCAN_BLK>>>();
    k_add_prefix<<<(Nn + 256) / 256, 256>>>();
    k_scatter<<<(Ee + 255) / 256, 256>>>(e_src, e_dst);

    // --- GAT layer 1 aggregation ---
    k_aggregate<true, false, true><<<warp_blocks, 256>>>(b_g1, nullptr, nullptr, nullptr, nullptr);

    // --- GAT layer 2 (+ fused energy MLP) ---
    k_gemm128<<<gemm_blocks, 256>>>(nullptr, 1, W_g2, att_src2, att_dst2, Nn);
    k_aggregate<false, true, false><<<warp_blocks, 256>>>(b_g2, Wp1, bp1, Wp2, bp2);

    // --- ragged attention pooling ---
    k_pool<<<Gg, 128>>>(node_pos);

    // --- classifier ---
    dim3 cg(2, Gg / 8);
    k_classify<<<cg, 128>>>(Wl, bl, out);
}

// round 15
// speedup vs baseline: 1.0962x; 1.0962x over previous
#include <cuda_runtime.h>
#include <cuda_fp16.h>
#include <cuda_bf16.h>
#include <cstdint>
#include <math.h>

// Problem constants (fixed dataset)
#define Nn 50000
#define Ee 600000
#define Hh 128
#define Gg 512
#define HPd 25
#define WTS 132          // padded WT row stride (floats); 132*4=528B, 16B multiple
#define Cc 1000
#define SCAN_BLK 1024
#define NBLK ((Nn + SCAN_BLK - 1) / SCAN_BLK)   // 49

// ---------------- device scratch ----------------
// INVARIANT: g_cnt and g_cur are all-zero on entry to kernel_launch.
// (BSS starts zeroed; k_scan_blocks re-zeros g_cnt, agg layer-1 re-zeros g_cur.)
__device__ __half g_h[Nn * Hh];     // h = x @ W (fp16, current layer)
__device__ float g_x[Nn * Hh];
__device__ float g_as[Nn];
__device__ float g_ad[Nn];
__device__ float g_energy[Nn];
__device__ int   g_cnt[Nn];
__device__ int   g_cur[Nn];
__device__ int   g_off[Nn + 1];
__device__ int   g_csr[Ee];
__device__ int   g_bsum[NBLK];
__device__ float g_pooled[Gg * Hh];

// ---------------- helpers ----------------
__device__ __forceinline__ float leaky(float v) { return v > 0.f ? v : 0.2f * v; }
__device__ __forceinline__ float wred_max(float v) {
    #pragma unroll
    for (int o = 16; o; o >>= 1) v = fmaxf(v, __shfl_xor_sync(0xffffffffu, v, o));
    return v;
}
__device__ __forceinline__ float wred_sum(float v) {
    #pragma unroll
    for (int o = 16; o; o >>= 1) v += __shfl_xor_sync(0xffffffffu, v, o);
    return v;
}
__device__ __forceinline__ float to_tf32(float v) {
    uint32_t u;
    asm("cvt.rna.tf32.f32 %0, %1;" : "=r"(u) : "f"(v));
    return __uint_as_float(u);
}
__device__ __forceinline__ void mma_tf32(float c[4], const uint32_t a[4], const uint32_t b[2]) {
    asm volatile(
        "mma.sync.aligned.m16n8k8.row.col.f32.tf32.tf32.f32 "
        "{%0,%1,%2,%3}, {%4,%5,%6,%7}, {%8,%9}, {%0,%1,%2,%3};"
        : "+f"(c[0]), "+f"(c[1]), "+f"(c[2]), "+f"(c[3])
        : "r"(a[0]), "r"(a[1]), "r"(a[2]), "r"(a[3]), "r"(b[0]), "r"(b[1]));
}

// ---------------- CSR build ----------------
__global__ void k_hist(const int* __restrict__ dst) {
    int i = blockIdx.x * blockDim.x + threadIdx.x;
    if (i < Ee) atomicAdd(&g_cnt[dst[i]], 1);
}

// parallel per-block scan (coalesced); re-zeros g_cnt after reading
__global__ void k_scan_blocks() {
    __shared__ int s[SCAN_BLK];
    int t = threadIdx.x;
    int i = blockIdx.x * SCAN_BLK + t;
    int v = (i < Nn) ? g_cnt[i] : 0;
    if (i < Nn) g_cnt[i] = 0;
    s[t] = v;
    __syncthreads();
    #pragma unroll
    for (int off = 1; off < SCAN_BLK; off <<= 1) {
        int x = 0;
        if (t >= off) x = s[t - off];
        __syncthreads();
        s[t] += x;
        __syncthreads();
    }
    if (i < Nn) g_off[i] = s[t] - v;          // exclusive within block
    if (t == SCAN_BLK - 1) g_bsum[blockIdx.x] = s[t];
}

// add cross-block prefix; each block computes the <=49-element bsum scan itself
__global__ void k_add_prefix() {
    __shared__ int pre[NBLK];
    int t = threadIdx.x;
    if (t < 32) {
        int l = t;
        int a = (l < NBLK) ? g_bsum[l] : 0;
        int b = (l + 32 < NBLK) ? g_bsum[l + 32] : 0;
        int A = a, B = b;
        #pragma unroll
        for (int o = 1; o < 32; o <<= 1) {
            int t1 = __shfl_up_sync(0xffffffffu, A, o);
            int t2 = __shfl_up_sync(0xffffffffu, B, o);
            if (l >= o) { A += t1; B += t2; }
        }
        int totA = __shfl_sync(0xffffffffu, A, 31);
        if (l < NBLK) pre[l] = A - a;
        if (l + 32 < NBLK) pre[l + 32] = totA + B - b;
    }
    __syncthreads();
    int i = blockIdx.x * blockDim.x + t;
    if (i < Nn) g_off[i] += pre[i >> 10];
    else if (i == Nn) g_off[Nn] = Ee;
}

__global__ void k_scatter(const int* __restrict__ src, const int* __restrict__ dst) {
    int i = blockIdx.x * blockDim.x + threadIdx.x;
    if (i < Ee) {
        int d = dst[i];
        int pos = g_off[d] + atomicAdd(&g_cur[d], 1);
        g_csr[pos] = src[i];
    }
}

// ---------------- TF32 tensor-core GEMM + fused attention dots ----------------
// g_h[M,128] (fp16) = X[M,128] @ W[128,128];  g_as = h.a_src, g_ad = h.a_dst
__global__ void __launch_bounds__(256) k_gemm128(
        const float* __restrict__ Xext, int src_sel,
        const float* __restrict__ W,
        const float* __restrict__ a_src, const float* __restrict__ a_dst, int M) {
    const float* __restrict__ X = src_sel ? (const float*)g_x : Xext;
    __shared__ __align__(16) float Xs[128][36];
    __shared__ __align__(16) float Ws[32][136];
    __shared__ __align__(16) float sd_as[2][128];
    __shared__ __align__(16) float sd_ad[2][128];

    int tid = threadIdx.x;
    int lane = tid & 31, wid = tid >> 5;
    int wm = wid >> 1, wn = wid & 1;
    int gid = lane >> 2, tig = lane & 3;
    int row0 = blockIdx.x * 128;

    float acc[2][8][4];
    #pragma unroll
    for (int mt = 0; mt < 2; mt++)
        #pragma unroll
        for (int nt = 0; nt < 8; nt++)
            #pragma unroll
            for (int q = 0; q < 4; q++) acc[mt][nt][q] = 0.f;

    #pragma unroll 1
    for (int kc = 0; kc < 4; kc++) {
        #pragma unroll
        for (int l = 0; l < 4; l++) {
            int f = tid + l * 256;
            int r = f >> 3, c4 = f & 7;
            int gr = row0 + r;
            float4 v = make_float4(0.f, 0.f, 0.f, 0.f);
            if (gr < M) v = reinterpret_cast<const float4*>(&X[gr * 128 + kc * 32])[c4];
            Xs[r][c4 * 4 + 0] = to_tf32(v.x);
            Xs[r][c4 * 4 + 1] = to_tf32(v.y);
            Xs[r][c4 * 4 + 2] = to_tf32(v.z);
            Xs[r][c4 * 4 + 3] = to_tf32(v.w);
        }
        #pragma unroll
        for (int l = 0; l < 4; l++) {
            int f = tid + l * 256;
            int k = f >> 5, c4 = f & 31;
            float4 v = reinterpret_cast<const float4*>(&W[(kc * 32 + k) * 128])[c4];
            Ws[k][c4 * 4 + 0] = to_tf32(v.x);
            Ws[k][c4 * 4 + 1] = to_tf32(v.y);
            Ws[k][c4 * 4 + 2] = to_tf32(v.z);
            Ws[k][c4 * 4 + 3] = to_tf32(v.w);
        }
        __syncthreads();
        #pragma unroll
        for (int ks = 0; ks < 4; ks++) {
            int k0 = ks * 8;
            uint32_t a[2][4];
            #pragma unroll
            for (int mt = 0; mt < 2; mt++) {
                int rb = wm * 32 + mt * 16;
                a[mt][0] = __float_as_uint(Xs[rb + gid][k0 + tig]);
                a[mt][1] = __float_as_uint(Xs[rb + gid + 8][k0 + tig]);
                a[mt][2] = __float_as_uint(Xs[rb + gid][k0 + tig + 4]);
                a[mt][3] = __float_as_uint(Xs[rb + gid + 8][k0 + tig + 4]);
            }
            uint32_t b[8][2];
            #pragma unroll
            for (int nt = 0; nt < 8; nt++) {
                int cb = wn * 64 + nt * 8 + gid;
                b[nt][0] = __float_as_uint(Ws[k0 + tig][cb]);
                b[nt][1] = __float_as_uint(Ws[k0 + tig + 4][cb]);
            }
            #pragma unroll
            for (int mt = 0; mt < 2; mt++)
                #pragma unroll
                for (int nt = 0; nt < 8; nt++)
                    mma_tf32(acc[mt][nt], a[mt], b[nt]);
        }
        __syncthreads();
    }

    // store h as fp16 (half2 per (mt,nt,half))
    #pragma unroll
    for (int mt = 0; mt < 2; mt++) {
        int r0 = row0 + wm * 32 + mt * 16 + gid;
        #pragma unroll
        for (int half = 0; half < 2; half++) {
            int gr = r0 + half * 8;
            if (gr < M) {
                #pragma unroll
                for (int nt = 0; nt < 8; nt++) {
                    int col = wn * 64 + nt * 8 + 2 * tig;
                    __half2 v = __floats2half2_rn(acc[mt][nt][2 * half + 0], acc[mt][nt][2 * half + 1]);
                    *reinterpret_cast<__half2*>(&g_h[gr * 128 + col]) = v;
                }
            }
        }
    }

    // fused attention dots
    float sa[8][2], sd[8][2];
    #pragma unroll
    for (int nt = 0; nt < 8; nt++) {
        int col = wn * 64 + nt * 8 + 2 * tig;
        sa[nt][0] = a_src[col]; sa[nt][1] = a_src[col + 1];
        sd[nt][0] = a_dst[col]; sd[nt][1] = a_dst[col + 1];
    }
    #pragma unroll
    for (int mt = 0; mt < 2; mt++) {
        #pragma unroll
        for (int half = 0; half < 2; half++) {
            float ps = 0.f, pd = 0.f;
            #pragma unroll
            for (int nt = 0; nt < 8; nt++) {
                ps += acc[mt][nt][2 * half + 0] * sa[nt][0] + acc[mt][nt][2 * half + 1] * sa[nt][1];
                pd += acc[mt][nt][2 * half + 0] * sd[nt][0] + acc[mt][nt][2 * half + 1] * sd[nt][1];
            }
            ps += __shfl_xor_sync(0xffffffffu, ps, 1);
            ps += __shfl_xor_sync(0xffffffffu, ps, 2);
            pd += __shfl_xor_sync(0xffffffffu, pd, 1);
            pd += __shfl_xor_sync(0xffffffffu, pd, 2);
            if (tig == 0) {
                int r = wm * 32 + mt * 16 + half * 8 + gid;
                sd_as[wn][r] = ps;
                sd_ad[wn][r] = pd;
            }
        }
    }
    __syncthreads();
    if (tid < 128) {
        int gr = row0 + tid;
        if (gr < M) {
            g_as[gr] = sd_as[0][tid] + sd_as[1][tid];
            g_ad[gr] = sd_ad[0][tid] + sd_ad[1][tid];
        }
    }
}

// ---------------- softmax aggregation (warp/node), online softmax, fp16 h ----------------
// ZEROCUR: also re-zero g_cur (consumed by k_scatter) to restore the entry invariant.
template <bool ELU, bool ENERGY, bool ZEROCUR>
__global__ void __launch_bounds__(256) k_aggregate(
        const float* __restrict__ bias,
        const float* __restrict__ Wp1, const float* __restrict__ bp1,
        const float* __restrict__ Wp2, const float* __restrict__ bp2) {
    __shared__ __align__(16) float WT[ENERGY ? HPd * WTS : 4];    // [p][128], stride 132
    __shared__ __align__(16) float sb1[ENERGY ? HPd : 4];
    __shared__ __align__(16) float sw2[ENERGY ? HPd : 4];
    __shared__ __align__(16) float sxrow[ENERGY ? 8 : 1][ENERGY ? 128 : 4];
    __shared__ float sb2[1];
    if (ZEROCUR) {
        int gi = blockIdx.x * blockDim.x + threadIdx.x;
        if (gi < Nn) g_cur[gi] = 0;
    }
    if (ENERGY) {
        for (int t = threadIdx.x; t < HPd * 128; t += blockDim.x) {
            int p = t >> 7, h = t & 127;
            WT[p * WTS + h] = Wp1[h * HPd + p];
        }
        if (threadIdx.x < HPd) { sb1[threadIdx.x] = bp1[threadIdx.x]; sw2[threadIdx.x] = Wp2[threadIdx.x]; }
        if (threadIdx.x == 0) sb2[0] = bp2[0];
        __syncthreads();
    }

    int wd = threadIdx.x >> 5;
    int w = (blockIdx.x * blockDim.x + threadIdx.x) >> 5;
    int lane = threadIdx.x & 31;
    if (w >= Nn) return;
    float adi = g_ad[w];
    float asi = g_as[w];
    int lo = g_off[w], hi = g_off[w + 1];

    float eself = leaky(asi + adi);
    // online pass: max + sum(exp), fast exp (MUFU)
    float m = (lane == 0) ? eself : -INFINITY;
    float ssum = (lane == 0) ? 1.f : 0.f;
    for (int j = lo + lane; j < hi; j += 32) {
        float e = leaky(g_as[g_csr[j]] + adi);
        if (e > m) { ssum *= __expf(m - e); m = e; }
        ssum += __expf(e - m);
    }
    float M = wred_max(m);
    ssum *= (m == -INFINITY) ? 0.f : __expf(m - M);
    ssum = wred_sum(ssum);
    float inv = 1.f / ssum;

    // weighted accumulate: lane owns 4 h-columns (one uint2 = 4 halves = 8B per row)
    const uint2* hp = reinterpret_cast<const uint2*>(g_h);
    float wself = __expf(eself - M) * inv;
    uint2 rself = hp[w * 32 + lane];
    float2 f0 = __half22float2(*reinterpret_cast<__half2*>(&rself.x));
    float2 f1 = __half22float2(*reinterpret_cast<__half2*>(&rself.y));
    float4 acc = make_float4(wself * f0.x, wself * f0.y, wself * f1.x, wself * f1.y);
    for (int base = lo; base < hi; base += 32) {
        int j = base + lane;
        int sj = 0;
        float wj = 0.f;
        if (j < hi) {
            sj = g_csr[j];
            wj = __expf(leaky(g_as[sj] + adi) - M) * inv;
        }
        int cnt = min(32, hi - base);
        for (int q = 0; q < cnt; q++) {
            int   s  = __shfl_sync(0xffffffffu, sj, q);
            float ww = __shfl_sync(0xffffffffu, wj, q);
            uint2 r = hp[s * 32 + lane];
            float2 v0 = __half22float2(*reinterpret_cast<__half2*>(&r.x));
            float2 v1 = __half22float2(*reinterpret_cast<__half2*>(&r.y));
            acc.x += ww * v0.x; acc.y += ww * v0.y;
            acc.z += ww * v1.x; acc.w += ww * v1.y;
        }
    }
    // lane owns cols [4*lane, 4*lane+4)
    float4 b = reinterpret_cast<const float4*>(bias)[lane];
    acc.x += b.x; acc.y += b.y; acc.z += b.z; acc.w += b.w;
    if (ELU) {
        // ELU via fast exp: exp(x)-1 for x<=0 (MUFU instead of libdevice expm1f)
        acc.x = acc.x > 0.f ? acc.x : __expf(acc.x) - 1.f;
        acc.y = acc.y > 0.f ? acc.y : __expf(acc.y) - 1.f;
        acc.z = acc.z > 0.f ? acc.z : __expf(acc.z) - 1.f;
        acc.w = acc.w > 0.f ? acc.w : __expf(acc.w) - 1.f;
    }
    reinterpret_cast<float4*>(g_x)[w * 32 + lane] = acc;

    if (ENERGY) {
        // stage x row in smem; lane p (<25) computes hidden unit p; single warp reduction
        reinterpret_cast<float4*>(&sxrow[wd][0])[lane] = acc;
        __syncwarp();
        float e = 0.f;
        if (lane < HPd) {
            float hid = sb1[lane];
            const float4* wt4 = reinterpret_cast<const float4*>(&WT[lane * WTS]);
            const float4* sx4 = reinterpret_cast<const float4*>(&sxrow[wd][0]);
            #pragma unroll 8
            for (int k4 = 0; k4 < 32; k4++) {
                float4 xv = sx4[k4];
                float4 wv = wt4[k4];
                hid += xv.x * wv.x + xv.y * wv.y + xv.z * wv.z + xv.w * wv.w;
            }
            e = fmaxf(hid, 0.f) * sw2[lane];
        }
        e = wred_sum(e);
        if (lane == 0) g_energy[w] = e + sb2[0];
    }
}

// ---------------- segment-softmax pooling (block per segment g) ----------------
__global__ void __launch_bounds__(128) k_pool(const int* __restrict__ node_pos) {
    __shared__ float red[128];
    __shared__ float sw[128];
    int g = blockIdx.x;
    int t = threadIdx.x;
    int lo = node_pos[g], hi = node_pos[g + 1];
    if (lo >= hi) { g_pooled[g * 128 + t] = 0.f; return; }

    float local = -INFINITY;
    for (int n = lo + t; n < hi; n += 128) local = fmaxf(local, g_energy[n]);
    red[t] = local; __syncthreads();
    #pragma unroll
    for (int o = 64; o; o >>= 1) { if (t < o) red[t] = fmaxf(red[t], red[t + o]); __syncthreads(); }
    float m = red[0]; __syncthreads();

    local = 0.f;
    for (int n = lo + t; n < hi; n += 128) local += expf(g_energy[n] - m);
    red[t] = local; __syncthreads();
    #pragma unroll
    for (int o = 64; o; o >>= 1) { if (t < o) red[t] += red[t + o]; __syncthreads(); }
    float inv = 1.f / red[0];
    __syncthreads();

    float acc = 0.f;
    for (int chunk = lo; chunk < hi; chunk += 128) {
        int n = chunk + t;
        sw[t] = (n < hi) ? expf(g_energy[n] - m) * inv : 0.f;
        __syncthreads();
        int cnt = min(128, hi - chunk);
        #pragma unroll 4
        for (int q = 0; q < cnt; q++)
            acc += sw[q] * g_x[(chunk + q) * 128 + t];
        __syncthreads();
    }
    g_pooled[g * 128 + t] = acc;
}

// ---------------- classifier: out[G,C] = pooled @ Wl + bl ----------------
__global__ void __launch_bounds__(128) k_classify(
        const float* __restrict__ Wl, const float* __restrict__ bl,
        float* __restrict__ out) {
    __shared__ __align__(16) float sp[8][128];
    int g0 = blockIdx.y * 8;
    int c4 = blockIdx.x * 128 + threadIdx.x;
    for (int t = threadIdx.x; t < 8 * 128; t += 128) {
        int gi = t >> 7, k = t & 127;
        sp[gi][k] = g_pooled[(g0 + gi) * 128 + k];
    }
    __syncthreads();
    if (c4 >= Cc / 4) return;
    float4 acc[8];
    float4 blv = reinterpret_cast<const float4*>(bl)[c4];
    #pragma unroll
    for (int gi = 0; gi < 8; gi++) acc[gi] = blv;
    #pragma unroll 4
    for (int k = 0; k < 128; k++) {
        float4 wv = reinterpret_cast<const float4*>(&Wl[k * Cc])[c4];
        #pragma unroll
        for (int gi = 0; gi < 8; gi++) {
            float s = sp[gi][k];
            acc[gi].x += s * wv.x; acc[gi].y += s * wv.y;
            acc[gi].z += s * wv.z; acc[gi].w += s * wv.w;
        }
    }
    #pragma unroll
    for (int gi = 0; gi < 8; gi++)
        reinterpret_cast<float4*>(&out[(g0 + gi) * Cc])[c4] = acc[gi];
}

// ---------------- launch ----------------
extern "C" void kernel_launch(void* const* d_in, const int* in_sizes, int n_in,
                              void* d_out, int out_size) {
    const float* cfg_nodes = (const float*)d_in[0];
    const int*   rel       = (const int*)  d_in[1];
    const int*   node_pos  = (const int*)  d_in[2];
    const float* W_g1      = (const float*)d_in[3];
    const float* att_src1  = (const float*)d_in[4];
    const float* att_dst1  = (const float*)d_in[5];
    const float* b_g1      = (const float*)d_in[6];
    const float* W_g2      = (const float*)d_in[7];
    const float* att_src2  = (const float*)d_in[8];
    const float* att_dst2  = (const float*)d_in[9];
    const float* b_g2      = (const float*)d_in[10];
    const float* Wp1       = (const float*)d_in[11];
    const float* bp1       = (const float*)d_in[12];
    const float* Wp2       = (const float*)d_in[13];
    const float* bp2       = (const float*)d_in[14];
    const float* Wl        = (const float*)d_in[15];
    const float* bl        = (const float*)d_in[16];
    float* out = (float*)d_out;

    const int* e_src = rel;
    const int* e_dst = rel + Ee;

    int gemm_blocks = (Nn + 127) / 128;
    int warp_blocks = (Nn + 7) / 8;

    // gemm1 first (needs only inputs)
    k_gemm128<<<gemm_blocks, 256>>>(cfg_nodes, 0, W_g1, att_src1, att_dst1, Nn);

    // --- CSR build (parallel scan, coalesced; bsum scan folded into add_prefix) ---
    k_hist<<<(Ee + 255) / 256, 256>>>(e_dst);
    k_scan_blocks<<<NBLK, SCAN_BLK>>>();
    k_add_prefix<<<(Nn + 256) / 256, 256>>>();
    k_scatter<<<(Ee + 255) / 256, 256>>>(e_src, e_dst);

    // --- GAT layer 1 aggregation ---
    k_aggregate<true, false, true><<<warp_blocks, 256>>>(b_g1, nullptr, nullptr, nullptr, nullptr);

    // --- GAT layer 2 (+ fused energy MLP) ---
    k_gemm128<<<gemm_blocks, 256>>>(nullptr, 1, W_g2, att_src2, att_dst2, Nn);
    k_aggregate<false, true, false><<<warp_blocks, 256>>>(b_g2, Wp1, bp1, Wp2, bp2);

    // --- ragged attention pooling ---
    k_pool<<<Gg, 128>>>(node_pos);

    // --- classifier ---
    dim3 cg(2, Gg / 8);
    k_classify<<<cg, 128>>>(Wl, bl, out);
}

// round 16
// speedup vs baseline: 1.1184x; 1.0203x over previous
#include <cuda_runtime.h>
#include <cuda_fp16.h>
#include <cuda_bf16.h>
#include <cstdint>
#include <math.h>

// Problem constants (fixed dataset)
#define Nn 50000
#define Ee 600000
#define Hh 128
#define Gg 512
#define HPd 25
#define WTS 132          // padded WT row stride (floats); 132*4=528B, 16B multiple
#define Cc 1000
#define SCAN_BLK 1024
#define NBLK ((Nn + SCAN_BLK - 1) / SCAN_BLK)   // 49

// ---------------- device scratch ----------------
// INVARIANT: g_cnt and g_cur are all-zero on entry to kernel_launch.
// (BSS starts zeroed; k_scan_blocks re-zeros g_cnt, agg layer-1 re-zeros g_cur.)
__device__ __half g_h[Nn * Hh];     // h = x @ W (fp16, current layer)
__device__ float g_x[Nn * Hh];
__device__ float g_as[Nn];
__device__ float g_ad[Nn];
__device__ float g_energy[Nn];
__device__ int   g_cnt[Nn];
__device__ int   g_cur[Nn];
__device__ int   g_off[Nn + 1];
__device__ int   g_csr[Ee];
__device__ int   g_bsum[NBLK];
__device__ float g_pooled[Gg * Hh];

// ---------------- helpers ----------------
__device__ __forceinline__ float leaky(float v) { return v > 0.f ? v : 0.2f * v; }
__device__ __forceinline__ float wred_max(float v) {
    #pragma unroll
    for (int o = 16; o; o >>= 1) v = fmaxf(v, __shfl_xor_sync(0xffffffffu, v, o));
    return v;
}
__device__ __forceinline__ float wred_sum(float v) {
    #pragma unroll
    for (int o = 16; o; o >>= 1) v += __shfl_xor_sync(0xffffffffu, v, o);
    return v;
}
__device__ __forceinline__ float to_tf32(float v) {
    uint32_t u;
    asm("cvt.rna.tf32.f32 %0, %1;" : "=r"(u) : "f"(v));
    return __uint_as_float(u);
}
__device__ __forceinline__ void mma_tf32(float c[4], const uint32_t a[4], const uint32_t b[2]) {
    asm volatile(
        "mma.sync.aligned.m16n8k8.row.col.f32.tf32.tf32.f32 "
        "{%0,%1,%2,%3}, {%4,%5,%6,%7}, {%8,%9}, {%0,%1,%2,%3};"
        : "+f"(c[0]), "+f"(c[1]), "+f"(c[2]), "+f"(c[3])
        : "r"(a[0]), "r"(a[1]), "r"(a[2]), "r"(a[3]), "r"(b[0]), "r"(b[1]));
}

// ---------------- CSR build ----------------
__global__ void k_hist(const int* __restrict__ dst) {
    int i = blockIdx.x * blockDim.x + threadIdx.x;
    if (i < Ee) atomicAdd(&g_cnt[dst[i]], 1);
}

// parallel per-block scan (coalesced); re-zeros g_cnt after reading
__global__ void k_scan_blocks() {
    __shared__ int s[SCAN_BLK];
    int t = threadIdx.x;
    int i = blockIdx.x * SCAN_BLK + t;
    int v = (i < Nn) ? g_cnt[i] : 0;
    if (i < Nn) g_cnt[i] = 0;
    s[t] = v;
    __syncthreads();
    #pragma unroll
    for (int off = 1; off < SCAN_BLK; off <<= 1) {
        int x = 0;
        if (t >= off) x = s[t - off];
        __syncthreads();
        s[t] += x;
        __syncthreads();
    }
    if (i < Nn) g_off[i] = s[t] - v;          // exclusive within block
    if (t == SCAN_BLK - 1) g_bsum[blockIdx.x] = s[t];
}

// add cross-block prefix; each block computes the <=49-element bsum scan itself
__global__ void k_add_prefix() {
    __shared__ int pre[NBLK];
    int t = threadIdx.x;
    if (t < 32) {
        int l = t;
        int a = (l < NBLK) ? g_bsum[l] : 0;
        int b = (l + 32 < NBLK) ? g_bsum[l + 32] : 0;
        int A = a, B = b;
        #pragma unroll
        for (int o = 1; o < 32; o <<= 1) {
            int t1 = __shfl_up_sync(0xffffffffu, A, o);
            int t2 = __shfl_up_sync(0xffffffffu, B, o);
            if (l >= o) { A += t1; B += t2; }
        }
        int totA = __shfl_sync(0xffffffffu, A, 31);
        if (l < NBLK) pre[l] = A - a;
        if (l + 32 < NBLK) pre[l + 32] = totA + B - b;
    }
    __syncthreads();
    int i = blockIdx.x * blockDim.x + t;
    if (i < Nn) g_off[i] += pre[i >> 10];
    else if (i == Nn) g_off[Nn] = Ee;
}

__global__ void k_scatter(const int* __restrict__ src, const int* __restrict__ dst) {
    int i = blockIdx.x * blockDim.x + threadIdx.x;
    if (i < Ee) {
        int d = dst[i];
        int pos = g_off[d] + atomicAdd(&g_cur[d], 1);
        g_csr[pos] = src[i];
    }
}

// ---------------- TF32 tensor-core GEMM + fused attention dots ----------------
// g_h[M,128] (fp16) = X[M,128] @ W[128,128];  g_as = h.a_src, g_ad = h.a_dst
__global__ void __launch_bounds__(256) k_gemm128(
        const float* __restrict__ Xext, int src_sel,
        const float* __restrict__ W,
        const float* __restrict__ a_src, const float* __restrict__ a_dst, int M) {
    const float* __restrict__ X = src_sel ? (const float*)g_x : Xext;
    __shared__ __align__(16) float Xs[128][36];
    __shared__ __align__(16) float Ws[32][136];
    __shared__ __align__(16) float sd_as[2][128];
    __shared__ __align__(16) float sd_ad[2][128];

    int tid = threadIdx.x;
    int lane = tid & 31, wid = tid >> 5;
    int wm = wid >> 1, wn = wid & 1;
    int gid = lane >> 2, tig = lane & 3;
    int row0 = blockIdx.x * 128;

    float acc[2][8][4];
    #pragma unroll
    for (int mt = 0; mt < 2; mt++)
        #pragma unroll
        for (int nt = 0; nt < 8; nt++)
            #pragma unroll
            for (int q = 0; q < 4; q++) acc[mt][nt][q] = 0.f;

    #pragma unroll 1
    for (int kc = 0; kc < 4; kc++) {
        #pragma unroll
        for (int l = 0; l < 4; l++) {
            int f = tid + l * 256;
            int r = f >> 3, c4 = f & 7;
            int gr = row0 + r;
            float4 v = make_float4(0.f, 0.f, 0.f, 0.f);
            if (gr < M) v = reinterpret_cast<const float4*>(&X[gr * 128 + kc * 32])[c4];
            Xs[r][c4 * 4 + 0] = to_tf32(v.x);
            Xs[r][c4 * 4 + 1] = to_tf32(v.y);
            Xs[r][c4 * 4 + 2] = to_tf32(v.z);
            Xs[r][c4 * 4 + 3] = to_tf32(v.w);
        }
        #pragma unroll
        for (int l = 0; l < 4; l++) {
            int f = tid + l * 256;
            int k = f >> 5, c4 = f & 31;
            float4 v = reinterpret_cast<const float4*>(&W[(kc * 32 + k) * 128])[c4];
            Ws[k][c4 * 4 + 0] = to_tf32(v.x);
            Ws[k][c4 * 4 + 1] = to_tf32(v.y);
            Ws[k][c4 * 4 + 2] = to_tf32(v.z);
            Ws[k][c4 * 4 + 3] = to_tf32(v.w);
        }
        __syncthreads();
        #pragma unroll
        for (int ks = 0; ks < 4; ks++) {
            int k0 = ks * 8;
            uint32_t a[2][4];
            #pragma unroll
            for (int mt = 0; mt < 2; mt++) {
                int rb = wm * 32 + mt * 16;
                a[mt][0] = __float_as_uint(Xs[rb + gid][k0 + tig]);
                a[mt][1] = __float_as_uint(Xs[rb + gid + 8][k0 + tig]);
                a[mt][2] = __float_as_uint(Xs[rb + gid][k0 + tig + 4]);
                a[mt][3] = __float_as_uint(Xs[rb + gid + 8][k0 + tig + 4]);
            }
            uint32_t b[8][2];
            #pragma unroll
            for (int nt = 0; nt < 8; nt++) {
                int cb = wn * 64 + nt * 8 + gid;
                b[nt][0] = __float_as_uint(Ws[k0 + tig][cb]);
                b[nt][1] = __float_as_uint(Ws[k0 + tig + 4][cb]);
            }
            #pragma unroll
            for (int mt = 0; mt < 2; mt++)
                #pragma unroll
                for (int nt = 0; nt < 8; nt++)
                    mma_tf32(acc[mt][nt], a[mt], b[nt]);
        }
        __syncthreads();
    }

    // store h as fp16 (half2 per (mt,nt,half))
    #pragma unroll
    for (int mt = 0; mt < 2; mt++) {
        int r0 = row0 + wm * 32 + mt * 16 + gid;
        #pragma unroll
        for (int half = 0; half < 2; half++) {
            int gr = r0 + half * 8;
            if (gr < M) {
                #pragma unroll
                for (int nt = 0; nt < 8; nt++) {
                    int col = wn * 64 + nt * 8 + 2 * tig;
                    __half2 v = __floats2half2_rn(acc[mt][nt][2 * half + 0], acc[mt][nt][2 * half + 1]);
                    *reinterpret_cast<__half2*>(&g_h[gr * 128 + col]) = v;
                }
            }
        }
    }

    // fused attention dots
    float sa[8][2], sd[8][2];
    #pragma unroll
    for (int nt = 0; nt < 8; nt++) {
        int col = wn * 64 + nt * 8 + 2 * tig;
        sa[nt][0] = a_src[col]; sa[nt][1] = a_src[col + 1];
        sd[nt][0] = a_dst[col]; sd[nt][1] = a_dst[col + 1];
    }
    #pragma unroll
    for (int mt = 0; mt < 2; mt++) {
        #pragma unroll
        for (int half = 0; half < 2; half++) {
            float ps = 0.f, pd = 0.f;
            #pragma unroll
            for (int nt = 0; nt < 8; nt++) {
                ps += acc[mt][nt][2 * half + 0] * sa[nt][0] + acc[mt][nt][2 * half + 1] * sa[nt][1];
                pd += acc[mt][nt][2 * half + 0] * sd[nt][0] + acc[mt][nt][2 * half + 1] * sd[nt][1];
            }
            ps += __shfl_xor_sync(0xffffffffu, ps, 1);
            ps += __shfl_xor_sync(0xffffffffu, ps, 2);
            pd += __shfl_xor_sync(0xffffffffu, pd, 1);
            pd += __shfl_xor_sync(0xffffffffu, pd, 2);
            if (tig == 0) {
                int r = wm * 32 + mt * 16 + half * 8 + gid;
                sd_as[wn][r] = ps;
                sd_ad[wn][r] = pd;
            }
        }
    }
    __syncthreads();
    if (tid < 128) {
        int gr = row0 + tid;
        if (gr < M) {
            g_as[gr] = sd_as[0][tid] + sd_as[1][tid];
            g_ad[gr] = sd_ad[0][tid] + sd_ad[1][tid];
        }
    }
}

// ---------------- softmax aggregation: SINGLE online pass (flash-style) ----------------
// ZEROCUR: also re-zero g_cur (consumed by k_scatter) to restore the entry invariant.
template <bool ELU, bool ENERGY, bool ZEROCUR>
__global__ void __launch_bounds__(256) k_aggregate(
        const float* __restrict__ bias,
        const float* __restrict__ Wp1, const float* __restrict__ bp1,
        const float* __restrict__ Wp2, const float* __restrict__ bp2) {
    __shared__ __align__(16) float WT[ENERGY ? HPd * WTS : 4];
    __shared__ __align__(16) float sb1[ENERGY ? HPd : 4];
    __shared__ __align__(16) float sw2[ENERGY ? HPd : 4];
    __shared__ __align__(16) float sxrow[ENERGY ? 8 : 1][ENERGY ? 128 : 4];
    __shared__ float sb2[1];
    if (ZEROCUR) {
        int gi = blockIdx.x * blockDim.x + threadIdx.x;
        if (gi < Nn) g_cur[gi] = 0;
    }
    if (ENERGY) {
        for (int t = threadIdx.x; t < HPd * 128; t += blockDim.x) {
            int p = t >> 7, h = t & 127;
            WT[p * WTS + h] = Wp1[h * HPd + p];
        }
        if (threadIdx.x < HPd) { sb1[threadIdx.x] = bp1[threadIdx.x]; sw2[threadIdx.x] = Wp2[threadIdx.x]; }
        if (threadIdx.x == 0) sb2[0] = bp2[0];
        __syncthreads();
    }

    int wd = threadIdx.x >> 5;
    int w = (blockIdx.x * blockDim.x + threadIdx.x) >> 5;
    int lane = threadIdx.x & 31;
    if (w >= Nn) return;
    float adi = g_ad[w];
    float asi = g_as[w];
    int lo = g_off[w], hi = g_off[w + 1];

    const uint2* hp = reinterpret_cast<const uint2*>(g_h);

    // self-loop seeds the online state: M = eself, unnormalized self weight = 1
    float M = leaky(asi + adi);          // warp-uniform
    float ssum = (lane == 0) ? 1.f : 0.f;  // per-lane partial of unnormalized sum
    uint2 rself = hp[w * 32 + lane];
    float2 f0 = __half22float2(*reinterpret_cast<__half2*>(&rself.x));
    float2 f1 = __half22float2(*reinterpret_cast<__half2*>(&rself.y));
    float4 acc = make_float4(f0.x, f0.y, f1.x, f1.y);   // weight exp(eself-M)=1

    for (int base = lo; base < hi; base += 32) {
        int j = base + lane;
        int sj = 0;
        float e = -INFINITY;
        if (j < hi) {
            sj = g_csr[j];
            e = leaky(g_as[sj] + adi);
        }
        float chunkM = wred_max(e);
        if (chunkM > M) {                 // warp-uniform branch
            float scale = __expf(M - chunkM);
            ssum *= scale;
            acc.x *= scale; acc.y *= scale; acc.z *= scale; acc.w *= scale;
            M = chunkM;
        }
        float wj = (j < hi) ? __expf(e - M) : 0.f;
        ssum += wj;
        int cnt = min(32, hi - base);
        for (int q = 0; q < cnt; q++) {
            int   s  = __shfl_sync(0xffffffffu, sj, q);
            float ww = __shfl_sync(0xffffffffu, wj, q);
            uint2 r = hp[s * 32 + lane];
            float2 v0 = __half22float2(*reinterpret_cast<__half2*>(&r.x));
            float2 v1 = __half22float2(*reinterpret_cast<__half2*>(&r.y));
            acc.x += ww * v0.x; acc.y += ww * v0.y;
            acc.z += ww * v1.x; acc.w += ww * v1.y;
        }
    }
    float inv = 1.f / wred_sum(ssum);
    acc.x *= inv; acc.y *= inv; acc.z *= inv; acc.w *= inv;

    // lane owns cols [4*lane, 4*lane+4)
    float4 b = reinterpret_cast<const float4*>(bias)[lane];
    acc.x += b.x; acc.y += b.y; acc.z += b.z; acc.w += b.w;
    if (ELU) {
        acc.x = acc.x > 0.f ? acc.x : __expf(acc.x) - 1.f;
        acc.y = acc.y > 0.f ? acc.y : __expf(acc.y) - 1.f;
        acc.z = acc.z > 0.f ? acc.z : __expf(acc.z) - 1.f;
        acc.w = acc.w > 0.f ? acc.w : __expf(acc.w) - 1.f;
    }
    reinterpret_cast<float4*>(g_x)[w * 32 + lane] = acc;

    if (ENERGY) {
        // stage x row in smem; lane p (<25) computes hidden unit p; single warp reduction
        reinterpret_cast<float4*>(&sxrow[wd][0])[lane] = acc;
        __syncwarp();
        float e = 0.f;
        if (lane < HPd) {
            float hid = sb1[lane];
            const float4* wt4 = reinterpret_cast<const float4*>(&WT[lane * WTS]);
            const float4* sx4 = reinterpret_cast<const float4*>(&sxrow[wd][0]);
            #pragma unroll 8
            for (int k4 = 0; k4 < 32; k4++) {
                float4 xv = sx4[k4];
                float4 wv = wt4[k4];
                hid += xv.x * wv.x + xv.y * wv.y + xv.z * wv.z + xv.w * wv.w;
            }
            e = fmaxf(hid, 0.f) * sw2[lane];
        }
        e = wred_sum(e);
        if (lane == 0) g_energy[w] = e + sb2[0];
    }
}

// ---------------- segment-softmax pooling (block per segment g) ----------------
__global__ void __launch_bounds__(128) k_pool(const int* __restrict__ node_pos) {
    __shared__ float red[128];
    __shared__ float sw[128];
    int g = blockIdx.x;
    int t = threadIdx.x;
    int lo = node_pos[g], hi = node_pos[g + 1];
    if (lo >= hi) { g_pooled[g * 128 + t] = 0.f; return; }

    float local = -INFINITY;
    for (int n = lo + t; n < hi; n += 128) local = fmaxf(local, g_energy[n]);
    red[t] = local; __syncthreads();
    #pragma unroll
    for (int o = 64; o; o >>= 1) { if (t < o) red[t] = fmaxf(red[t], red[t + o]); __syncthreads(); }
    float m = red[0]; __syncthreads();

    local = 0.f;
    for (int n = lo + t; n < hi; n += 128) local += expf(g_energy[n] - m);
    red[t] = local; __syncthreads();
    #pragma unroll
    for (int o = 64; o; o >>= 1) { if (t < o) red[t] += red[t + o]; __syncthreads(); }
    float inv = 1.f / red[0];
    __syncthreads();

    float acc = 0.f;
    for (int chunk = lo; chunk < hi; chunk += 128) {
        int n = chunk + t;
        sw[t] = (n < hi) ? expf(g_energy[n] - m) * inv : 0.f;
        __syncthreads();
        int cnt = min(128, hi - chunk);
        #pragma unroll 4
        for (int q = 0; q < cnt; q++)
            acc += sw[q] * g_x[(chunk + q) * 128 + t];
        __syncthreads();
    }
    g_pooled[g * 128 + t] = acc;
}

// ---------------- classifier: out[G,C] = pooled @ Wl + bl ----------------
__global__ void __launch_bounds__(128) k_classify(
        const float* __restrict__ Wl, const float* __restrict__ bl,
        float* __restrict__ out) {
    __shared__ __align__(16) float sp[8][128];
    int g0 = blockIdx.y * 8;
    int c4 = blockIdx.x * 128 + threadIdx.x;
    for (int t = threadIdx.x; t < 8 * 128; t += 128) {
        int gi = t >> 7, k = t & 127;
        sp[gi][k] = g_pooled[(g0 + gi) * 128 + k];
    }
    __syncthreads();
    if (c4 >= Cc / 4) return;
    float4 acc[8];
    float4 blv = reinterpret_cast<const float4*>(bl)[c4];
    #pragma unroll
    for (int gi = 0; gi < 8; gi++) acc[gi] = blv;
    #pragma unroll 4
    for (int k = 0; k < 128; k++) {
        float4 wv = reinterpret_cast<const float4*>(&Wl[k * Cc])[c4];
        #pragma unroll
        for (int gi = 0; gi < 8; gi++) {
            float s = sp[gi][k];
            acc[gi].x += s * wv.x; acc[gi].y += s * wv.y;
            acc[gi].z += s * wv.z; acc[gi].w += s * wv.w;
        }
    }
    #pragma unroll
    for (int gi = 0; gi < 8; gi++)
        reinterpret_cast<float4*>(&out[(g0 + gi) * Cc])[c4] = acc[gi];
}

// ---------------- launch ----------------
extern "C" void kernel_launch(void* const* d_in, const int* in_sizes, int n_in,
                              void* d_out, int out_size) {
    const float* cfg_nodes = (const float*)d_in[0];
    const int*   rel       = (const int*)  d_in[1];
    const int*   node_pos  = (const int*)  d_in[2];
    const float* W_g1      = (const float*)d_in[3];
    const float* att_src1  = (const float*)d_in[4];
    const float* att_dst1  = (const float*)d_in[5];
    const float* b_g1      = (const float*)d_in[6];
    const float* W_g2      = (const float*)d_in[7];
    const float* att_src2  = (const float*)d_in[8];
    const float* att_dst2  = (const float*)d_in[9];
    const float* b_g2      = (const float*)d_in[10];
    const float* Wp1       = (const float*)d_in[11];
    const float* bp1       = (const float*)d_in[12];
    const float* Wp2       = (const float*)d_in[13];
    const float* bp2       = (const float*)d_in[14];
    const float* Wl        = (const float*)d_in[15];
    const float* bl        = (const float*)d_in[16];
    float* out = (float*)d_out;

    const int* e_src = rel;
    const int* e_dst = rel + Ee;

    int gemm_blocks = (Nn + 127) / 128;
    int warp_blocks = (Nn + 7) / 8;

    // gemm1 first (needs only inputs)
    k_gemm128<<<gemm_blocks, 256>>>(cfg_nodes, 0, W_g1, att_src1, att_dst1, Nn);

    // --- CSR build (parallel scan, coalesced; bsum scan folded into add_prefix) ---
    k_hist<<<(Ee + 255) / 256, 256>>>(e_dst);
    k_scan_blocks<<<NBLK, SCAN_BLK>>>();
    k_add_prefix<<<(Nn + 256) / 256, 256>>>();
    k_scatter<<<(Ee + 255) / 256, 256>>>(e_src, e_dst);

    // --- GAT layer 1 aggregation ---
    k_aggregate<true, false, true><<<warp_blocks, 256>>>(b_g1, nullptr, nullptr, nullptr, nullptr);

    // --- GAT layer 2 (+ fused energy MLP) ---
    k_gemm128<<<gemm_blocks, 256>>>(nullptr, 1, W_g2, att_src2, att_dst2, Nn);
    k_aggregate<false, true, false><<<warp_blocks, 256>>>(b_g2, Wp1, bp1, Wp2, bp2);

    // --- ragged attention pooling ---
    k_pool<<<Gg, 128>>>(node_pos);

    // --- classifier ---
    dim3 cg(2, Gg / 8);
    k_classify<<<cg, 128>>>(Wl, bl, out);
}